// round 15
// baseline (speedup 1.0000x reference)
#include <cuda_runtime.h>
#include <math_constants.h>

// Problem constants (fixed by the dataset: B=32, N=2048)
#define BATCH 32
#define NPTS  2048
#define TPB   256
#define NWARP (TPB / 32)           // 8 warps per block
#define BPB   32                   // blocks (chunks) per batch
#define ROWS  64                   // rows per block
#define GRID  (BATCH * BPB)        // 1024
#define MRW   (NPTS / NWARP)       // m-range per warp = 256
#define GPW   (MRW / 4)            // 64 groups of 4 points per warp

__device__ double g_partial[GRID];
__device__ unsigned int g_count = 0;

typedef unsigned long long u64;

__device__ __forceinline__ u64 pack2(float lo, float hi) {
    u64 r;
    asm("mov.b64 %0, {%1, %2};" : "=l"(r) : "f"(lo), "f"(hi));
    return r;
}
__device__ __forceinline__ void unpack2(u64 v, float& lo, float& hi) {
    asm("mov.b64 {%0, %1}, %2;" : "=f"(lo), "=f"(hi) : "l"(v));
}
__device__ __forceinline__ u64 ffma2(u64 a, u64 b, u64 c) {
    u64 d;
    asm("fma.rn.f32x2 %0, %1, %2, %3;" : "=l"(d) : "l"(a), "l"(b), "l"(c));
    return d;
}

__device__ __forceinline__ void quat2mat(const float* __restrict__ q, float* R) {
    float w = q[0], x = q[1], y = q[2], z = q[3];
    float inv = 1.0f / sqrtf(w * w + x * x + y * y + z * z);
    w *= inv; x *= inv; y *= inv; z *= inv;
    R[0] = 1.f - 2.f * (y * y + z * z); R[1] = 2.f * (x * y - w * z); R[2] = 2.f * (x * z + w * y);
    R[3] = 2.f * (x * y + w * z);       R[4] = 1.f - 2.f * (x * x + z * z); R[5] = 2.f * (y * z - w * x);
    R[6] = 2.f * (x * z - w * y);       R[7] = 2.f * (y * z + w * x);       R[8] = 1.f - 2.f * (x * x + y * y);
}

__global__ void __launch_bounds__(TPB)
pts_loss_kernel(const float* __restrict__ q_est,
                const float* __restrict__ q_gt,
                const float* __restrict__ pts,
                const int*   __restrict__ sym,
                float* __restrict__ out)
{
    // Interleaved mapping: consecutive blocks -> different batches.
    const int b     = blockIdx.x % BATCH;
    const int chunk = blockIdx.x / BATCH;
    const int tid   = threadIdx.x;
    const int wid   = tid >> 5;
    const int lid   = tid & 31;

    // Interleaved SoA table: group g of 4 points -> 64 contiguous bytes
    // [x0..x3][y0..y3][z0..z3][w0..w3].
    __shared__ __align__(16) float s_tab[NPTS * 4];   // 32 KB
    __shared__ float s_min[NWARP][ROWS];
    __shared__ float s_xx[ROWS];
    __shared__ float red[TPB];

    float Re[9], Rg[9];
    quat2mat(q_est + 4 * b, Re);
    quat2mat(q_gt  + 4 * b, Rg);

    const float* __restrict__ P = pts + (size_t)b * NPTS * 3;
    const bool is_sym = (sym[b] != 0);

    float local = 0.0f;

    if (!is_sym) {
        if (tid < ROWS) {
            float D[9];
            #pragma unroll
            for (int i = 0; i < 9; i++) D[i] = Re[i] - Rg[i];
            const int n = chunk * ROWS + tid;
            const float p0 = P[3 * n], p1 = P[3 * n + 1], p2 = P[3 * n + 2];
            const float e0 = D[0] * p0 + D[1] * p1 + D[2] * p2;
            const float e1 = D[3] * p0 + D[4] * p1 + D[5] * p2;
            const float e2 = D[6] * p0 + D[7] * p1 + D[8] * p2;
            local = e0 * e0 + e1 * e1 + e2 * e2;
        }
    } else {
        // Hoist this lane's row points (global loads overlap the table build).
        const int nA = chunk * ROWS + lid;
        const int nB = nA + 32;
        const float pA0 = __ldg(P + 3 * nA), pA1 = __ldg(P + 3 * nA + 1), pA2 = __ldg(P + 3 * nA + 2);
        const float pB0 = __ldg(P + 3 * nB), pB1 = __ldg(P + 3 * nB + 1), pB2 = __ldg(P + 3 * nB + 2);

        // Build interleaved y-table: (-2*y0, -2*y1, -2*y2, yy)
        for (int m = tid; m < NPTS; m += TPB) {
            const float p0 = P[3 * m], p1 = P[3 * m + 1], p2 = P[3 * m + 2];
            const float y0 = Rg[0] * p0 + Rg[1] * p1 + Rg[2] * p2;
            const float y1 = Rg[3] * p0 + Rg[4] * p1 + Rg[5] * p2;
            const float y2 = Rg[6] * p0 + Rg[7] * p1 + Rg[8] * p2;
            const int g = m >> 2, j = m & 3;
            float* t = s_tab + g * 16;
            t[j]      = -2.f * y0;
            t[j + 4]  = -2.f * y1;
            t[j + 8]  = -2.f * y2;
            t[j + 12] = y0 * y0 + y1 * y1 + y2 * y2;
        }

        const float xA0 = Re[0] * pA0 + Re[1] * pA1 + Re[2] * pA2;
        const float xA1 = Re[3] * pA0 + Re[4] * pA1 + Re[5] * pA2;
        const float xA2 = Re[6] * pA0 + Re[7] * pA1 + Re[8] * pA2;
        const float xB0 = Re[0] * pB0 + Re[1] * pB1 + Re[2] * pB2;
        const float xB1 = Re[3] * pB0 + Re[4] * pB1 + Re[5] * pB2;
        const float xB2 = Re[6] * pB0 + Re[7] * pB1 + Re[8] * pB2;
        const u64 XA0 = pack2(xA0, xA0), XA1 = pack2(xA1, xA1), XA2 = pack2(xA2, xA2);
        const u64 XB0 = pack2(xB0, xB0), XB1 = pack2(xB1, xB1), XB2 = pack2(xB2, xB2);
        if (wid == 0) {
            s_xx[lid]      = xA0 * xA0 + xA1 * xA1 + xA2 * xA2;
            s_xx[lid + 32] = xB0 * xB0 + xB1 * xB1 + xB2 * xB2;
        }
        __syncthreads();

        float mA0 = CUDART_INF_F, mA1 = CUDART_INF_F, mA2 = CUDART_INF_F, mA3 = CUDART_INF_F;
        float mB0 = CUDART_INF_F, mB1 = CUDART_INF_F, mB2 = CUDART_INF_F, mB3 = CUDART_INF_F;

        const ulonglong2* __restrict__ q = (const ulonglong2*)(s_tab + wid * (GPW * 16));

        // ---- Software-pipelined scan: prefetch group g+1 before computing g.
        ulonglong2 vx = q[0], vy = q[1], vz = q[2], vw = q[3];

        #pragma unroll 4
        for (int g = 0; g < GPW - 1; g++) {
            // Prefetch next group (4 x LDS.128) — no consumer for ~40 instrs.
            const ulonglong2 nx = q[(g + 1) * 4 + 0];
            const ulonglong2 ny = q[(g + 1) * 4 + 1];
            const ulonglong2 nz = q[(g + 1) * 4 + 2];
            const ulonglong2 nw = q[(g + 1) * 4 + 3];

            float a, c, d, e;
            unpack2(ffma2(vx.x, XA0, ffma2(vy.x, XA1, ffma2(vz.x, XA2, vw.x))), a, c);
            unpack2(ffma2(vx.y, XA0, ffma2(vy.y, XA1, ffma2(vz.y, XA2, vw.y))), d, e);
            mA0 = fminf(mA0, a); mA1 = fminf(mA1, c); mA2 = fminf(mA2, d); mA3 = fminf(mA3, e);
            unpack2(ffma2(vx.x, XB0, ffma2(vy.x, XB1, ffma2(vz.x, XB2, vw.x))), a, c);
            unpack2(ffma2(vx.y, XB0, ffma2(vy.y, XB1, ffma2(vz.y, XB2, vw.y))), d, e);
            mB0 = fminf(mB0, a); mB1 = fminf(mB1, c); mB2 = fminf(mB2, d); mB3 = fminf(mB3, e);

            vx = nx; vy = ny; vz = nz; vw = nw;   // renamed under unroll
        }
        {   // epilogue: last group
            float a, c, d, e;
            unpack2(ffma2(vx.x, XA0, ffma2(vy.x, XA1, ffma2(vz.x, XA2, vw.x))), a, c);
            unpack2(ffma2(vx.y, XA0, ffma2(vy.y, XA1, ffma2(vz.y, XA2, vw.y))), d, e);
            mA0 = fminf(mA0, a); mA1 = fminf(mA1, c); mA2 = fminf(mA2, d); mA3 = fminf(mA3, e);
            unpack2(ffma2(vx.x, XB0, ffma2(vy.x, XB1, ffma2(vz.x, XB2, vw.x))), a, c);
            unpack2(ffma2(vx.y, XB0, ffma2(vy.y, XB1, ffma2(vz.y, XB2, vw.y))), d, e);
            mB0 = fminf(mB0, a); mB1 = fminf(mB1, c); mB2 = fminf(mB2, d); mB3 = fminf(mB3, e);
        }

        s_min[wid][lid]      = fminf(fminf(mA0, mA1), fminf(mA2, mA3));
        s_min[wid][lid + 32] = fminf(fminf(mB0, mB1), fminf(mB2, mB3));
        __syncthreads();

        if (tid < ROWS) {
            float mm = s_min[0][tid];
            #pragma unroll
            for (int w = 1; w < NWARP; w++) mm = fminf(mm, s_min[w][tid]);
            local = s_xx[tid] + mm;
        }
    }

    // Deterministic block reduction
    red[tid] = local;
    __syncthreads();
    #pragma unroll
    for (int s = TPB / 2; s > 0; s >>= 1) {
        if (tid < s) red[tid] += red[tid + s];
        __syncthreads();
    }

    // Fused finalize: last block reduces all partials (fixed order).
    __shared__ bool is_last;
    if (tid == 0) {
        g_partial[blockIdx.x] = (double)red[0];
        __threadfence();
        unsigned int c = atomicAdd(&g_count, 1u);
        is_last = (c == GRID - 1);
    }
    __syncthreads();

    if (is_last) {
        __shared__ double sd[TPB];
        double acc = 0.0;
        #pragma unroll
        for (int i = 0; i < GRID / TPB; i++)
            acc += g_partial[tid + i * TPB];
        sd[tid] = acc;
        __syncthreads();
        #pragma unroll
        for (int s = TPB / 2; s > 0; s >>= 1) {
            if (tid < s) sd[tid] += sd[tid + s];
            __syncthreads();
        }
        if (tid == 0) {
            out[0] = (float)(sd[0] / (2.0 * (double)NPTS * (double)BATCH));
            g_count = 0;   // reset for next (graph-replayed) call
        }
    }
}

extern "C" void kernel_launch(void* const* d_in, const int* in_sizes, int n_in,
                              void* d_out, int out_size)
{
    // metadata order: q_est(32x4), q_gt(32x4), T(32x3, unused), pts(32x2048x3), symmetries(32x1 int32)
    const float* q_est = (const float*)d_in[0];
    const float* q_gt  = (const float*)d_in[1];
    const float* pts   = (const float*)d_in[3];
    const int*   sym   = (const int*)d_in[4];
    float* out = (float*)d_out;

    pts_loss_kernel<<<GRID, TPB>>>(q_est, q_gt, pts, sym, out);
}